// round 12
// baseline (speedup 1.0000x reference)
#include <cuda_runtime.h>
#include <cuda_bf16.h>
#include <math.h>
#include <stdint.h>

#define BATCH 32
#define NPTS  8192
#define SAM1  512
#define SAK1  32
#define SAM2  128
#define SAK2  64

// ---------------- static scratch (no runtime allocation) ----------------
__device__ float g_xyz [BATCH*NPTS*3];
__device__ float g_new1[BATCH*SAM1*3];
__device__ float g_new2[BATCH*SAM2*3];
__device__ int   g_idx1[BATCH*SAM1*SAK1];
__device__ int   g_idx2[BATCH*SAM2*SAK2];
__device__ float g_pool[BATCH*1024];
__device__ float g_gl1 [BATCH*512];
__device__ float g_gl2 [BATCH*256];
// bf16 hi/lo activation planes
__device__ __align__(16) __nv_bfloat16 g_INh[35651584], g_INl[35651584]; // 262144x136 max
__device__ __align__(16) __nv_bfloat16 g_P0h[33554432], g_P0l[33554432]; // 524288x64 max
__device__ __align__(16) __nv_bfloat16 g_P1h[33554432], g_P1l[33554432];
__device__ __align__(16) __nv_bfloat16 g_F1h[2097152],  g_F1l[2097152];  // 16384x128
__device__ __align__(16) __nv_bfloat16 g_F2h[1048576],  g_F2l[1048576];  // 4096x256
__device__ __align__(16) __nv_bfloat16 g_Wh [1048576],  g_Wl [1048576];  // all weights

__device__ __forceinline__ uint32_t smem_u32(const void* p) {
    uint32_t a;
    asm("{ .reg .u64 t; cvta.to.shared.u64 t, %1; cvt.u32.u64 %0, t; }" : "=r"(a) : "l"(p));
    return a;
}
__device__ __forceinline__ void split1(float v, __nv_bfloat16& h, __nv_bfloat16& l) {
    h = __float2bfloat16(v);
    l = __float2bfloat16(v - __bfloat162float(h));
}
__device__ __forceinline__ void split2(float a, float b, uint32_t& hi, uint32_t& lo) {
    __nv_bfloat16 ha, la, hb, lb;
    split1(a, ha, la); split1(b, hb, lb);
    hi = ((uint32_t)__bfloat16_as_ushort(hb) << 16) | __bfloat16_as_ushort(ha);
    lo = ((uint32_t)__bfloat16_as_ushort(lb) << 16) | __bfloat16_as_ushort(la);
}
__device__ __forceinline__ void ldm_x4(uint32_t* r, uint32_t addr) {
    asm volatile("ldmatrix.sync.aligned.m8n8.x4.shared.b16 {%0,%1,%2,%3}, [%4];"
                 : "=r"(r[0]), "=r"(r[1]), "=r"(r[2]), "=r"(r[3]) : "r"(addr));
}
__device__ __forceinline__ void ldm_x2(uint32_t* r, uint32_t addr) {
    asm volatile("ldmatrix.sync.aligned.m8n8.x2.shared.b16 {%0,%1}, [%2];"
                 : "=r"(r[0]), "=r"(r[1]) : "r"(addr));
}
__device__ __forceinline__ void mma16816(float* c, const uint32_t* a, const uint32_t* b) {
    asm volatile(
        "mma.sync.aligned.m16n8k16.row.col.f32.bf16.bf16.f32 "
        "{%0,%1,%2,%3}, {%4,%5,%6,%7}, {%8,%9}, {%0,%1,%2,%3};"
        : "+f"(c[0]), "+f"(c[1]), "+f"(c[2]), "+f"(c[3])
        : "r"(a[0]), "r"(a[1]), "r"(a[2]), "r"(a[3]), "r"(b[0]), "r"(b[1]));
}

// =====================================================================
// warp-MMA GEMM on pre-split bf16 planes.
// C[M,N] = relu(A @ W^T + bias); A row stride Ks (=Kpad, mult of 8).
// Tile 128x64, BK=32, 256 threads (8 warps 4x2), 3-term hi/lo split.
// poolk>0: fused max over poolk-row groups. fp32out: write fp32 to outF,
// else write bf16 hi/lo planes (row stride N).
// =====================================================================
__global__ void __launch_bounds__(256)
k_wmma(const __nv_bfloat16* __restrict__ Ahi, const __nv_bfloat16* __restrict__ Alo,
       const __nv_bfloat16* __restrict__ Whi, const __nv_bfloat16* __restrict__ Wlo,
       const float* __restrict__ bias, float* __restrict__ outF,
       __nv_bfloat16* __restrict__ outHi, __nv_bfloat16* __restrict__ outLo,
       int M, int N, int Ks, int poolk, int fp32out) {
    constexpr int STR = 40;                       // bf16 row stride (80B)
    __shared__ __align__(16) char sraw[34816];
    __shared__ float sbias[64];
    __nv_bfloat16 (*Ah)[STR] = reinterpret_cast<__nv_bfloat16(*)[STR]>(sraw);
    __nv_bfloat16 (*Al)[STR] = reinterpret_cast<__nv_bfloat16(*)[STR]>(sraw + 10240);
    __nv_bfloat16 (*Bh)[STR] = reinterpret_cast<__nv_bfloat16(*)[STR]>(sraw + 20480);
    __nv_bfloat16 (*Bl)[STR] = reinterpret_cast<__nv_bfloat16(*)[STR]>(sraw + 25600);
    float (*epi)[68] = reinterpret_cast<float(*)[68]>(sraw);

    const int tid = threadIdx.x, lane = tid & 31, wid = tid >> 5;
    const int wm = wid & 3, wn = wid >> 2;
    const int m0 = blockIdx.x * 128, n0 = blockIdx.y * 64;

    if (tid < 64) sbias[tid] = (n0 + tid < N) ? bias[n0 + tid] : 0.f;

    float acc[2][4][4];
#pragma unroll
    for (int mt = 0; mt < 2; mt++)
#pragma unroll
        for (int nt = 0; nt < 4; nt++)
#pragma unroll
            for (int v = 0; v < 4; v++) acc[mt][nt][v] = 0.f;

    const uint4 z4 = make_uint4(0, 0, 0, 0);
    const int nchunks = (Ks + 31) >> 5;
    for (int ck = 0; ck < nchunks; ck++) {
        const int kb = ck << 5;
#pragma unroll
        for (int j = 0; j < 2; j++) {             // A: 128 rows x 4 groups-of-8
            int i = tid + j*256;
            int r = i >> 2, g = i & 3;
            int gm = m0 + r, gk = kb + g*8;
            uint4 vh = z4, vl = z4;
            if (gm < M && gk < Ks) {
                size_t o = (size_t)gm*Ks + gk;
                vh = *(const uint4*)&Ahi[o];
                vl = *(const uint4*)&Alo[o];
            }
            *(uint4*)&Ah[r][g*8] = vh;
            *(uint4*)&Al[r][g*8] = vl;
        }
        {                                          // B: 64 rows x 4 groups-of-8
            int r = tid >> 2, g = tid & 3;
            int gn = n0 + r, gk = kb + g*8;
            uint4 vh = z4, vl = z4;
            if (gn < N && gk < Ks) {
                size_t o = (size_t)gn*Ks + gk;
                vh = *(const uint4*)&Whi[o];
                vl = *(const uint4*)&Wlo[o];
            }
            *(uint4*)&Bh[r][g*8] = vh;
            *(uint4*)&Bl[r][g*8] = vl;
        }
        __syncthreads();

#pragma unroll
        for (int ks = 0; ks < 32; ks += 16) {
            uint32_t ah[2][4], al[2][4];
#pragma unroll
            for (int mt = 0; mt < 2; mt++) {
                int row = wm*32 + mt*16 + (lane & 7) + ((lane >> 3) & 1)*8;
                int kc  = ks + (lane >> 4)*8;
                ldm_x4(ah[mt], smem_u32(&Ah[row][kc]));
                ldm_x4(al[mt], smem_u32(&Al[row][kc]));
            }
            uint32_t bh[4][2], bl[4][2];
#pragma unroll
            for (int nt = 0; nt < 4; nt++) {
                int nr = wn*32 + nt*8 + (lane & 7);
                int kc = ks + ((lane >> 3) & 1)*8;
                ldm_x2(bh[nt], smem_u32(&Bh[nr][kc]));
                ldm_x2(bl[nt], smem_u32(&Bl[nr][kc]));
            }
#pragma unroll
            for (int mt = 0; mt < 2; mt++)
#pragma unroll
                for (int nt = 0; nt < 4; nt++) {
                    mma16816(acc[mt][nt], ah[mt], bh[nt]);
                    mma16816(acc[mt][nt], ah[mt], bl[nt]);
                    mma16816(acc[mt][nt], al[mt], bh[nt]);
                }
        }
        __syncthreads();
    }

    // ---- epilogue: bias + relu -> padded smem ----
    {
        int gid = lane >> 2, tig = lane & 3;
#pragma unroll
        for (int mt = 0; mt < 2; mt++)
#pragma unroll
            for (int nt = 0; nt < 4; nt++) {
                int r0 = wm*32 + mt*16 + gid;
                int cc = wn*32 + nt*8 + tig*2;
                epi[r0    ][cc    ] = fmaxf(acc[mt][nt][0] + sbias[cc    ], 0.f);
                epi[r0    ][cc + 1] = fmaxf(acc[mt][nt][1] + sbias[cc + 1], 0.f);
                epi[r0 + 8][cc    ] = fmaxf(acc[mt][nt][2] + sbias[cc    ], 0.f);
                epi[r0 + 8][cc + 1] = fmaxf(acc[mt][nt][3] + sbias[cc + 1], 0.f);
            }
    }
    __syncthreads();

    if (poolk == 0) {
        // bf16 plane output, 8-col vector stores
#pragma unroll
        for (int j = 0; j < 4; j++) {
            int i = tid + j*256;                  // 1024 groups
            int r = i >> 3, g = i & 7;
            int gm = m0 + r;
            if (gm < M) {
                const float* e = &epi[r][g*8];
                uint32_t h0,l0,h1,l1,h2,l2,h3,l3;
                split2(e[0], e[1], h0, l0);
                split2(e[2], e[3], h1, l1);
                split2(e[4], e[5], h2, l2);
                split2(e[6], e[7], h3, l3);
                size_t o = (size_t)gm*N + n0 + g*8;
                *(uint4*)&outHi[o] = make_uint4(h0, h1, h2, h3);
                *(uint4*)&outLo[o] = make_uint4(l0, l1, l2, l3);
            }
        }
    } else {
        int ng = 128 / poolk;
        for (int idx = tid; idx < 64*ng; idx += 256) {
            int c = idx & 63, g = idx >> 6;
            float mv = epi[g*poolk][c];
            for (int r = 1; r < poolk; r++) mv = fmaxf(mv, epi[g*poolk + r][c]);
            size_t o = (size_t)(m0/poolk + g)*N + n0 + c;
            if (fp32out) {
                outF[o] = mv;
            } else {
                __nv_bfloat16 h, l;
                split1(mv, h, l);
                outHi[o] = h; outLo[o] = l;
            }
        }
    }
}

// ---------------- weight split: W[N,K] fp32 -> bf16 hi/lo @ stride Kpad ----------------
__global__ void k_wsplit(const float* __restrict__ W, __nv_bfloat16* __restrict__ hi,
                         __nv_bfloat16* __restrict__ lo, int N, int K, int Kpad) {
    int i = blockIdx.x * blockDim.x + threadIdx.x;
    if (i >= N*Kpad) return;
    int n = i / Kpad, c = i - n*Kpad;
    float v = (c < K) ? W[(size_t)n*K + c] : 0.f;
    __nv_bfloat16 h, l;
    split1(v, h, l);
    hi[i] = h; lo[i] = l;
}

// ---------------- transpose [B,3,N] -> [B,N,3] ----------------
__global__ void k_transpose(const float* __restrict__ pts, float* __restrict__ xyz) {
    int i = blockIdx.x * blockDim.x + threadIdx.x;
    if (i >= BATCH*3*NPTS) return;
    int b = i / (3*NPTS);
    int r = i - b*3*NPTS;
    int c = r / NPTS;
    int n = r - c*NPTS;
    xyz[((size_t)b*NPTS + n)*3 + c] = pts[i];
}

// ---------------- farthest point sampling ----------------
template<int NPT, int NTH>
__global__ void k_fps(const float* __restrict__ xyz, float* __restrict__ out_xyz,
                      int n, int m) {
    constexpr int NW = NTH/32;
    int b = blockIdx.x;
    const float* px = xyz + (size_t)b*n*3;
    float* out = out_xyz + (size_t)b*m*3;
    int t = threadIdx.x, lane = t & 31, w = t >> 5;

    float X[NPT], Y[NPT], Z[NPT], D[NPT];
#pragma unroll
    for (int i = 0; i < NPT; i++) {
        int p = t + i*NTH;
        X[i] = px[p*3]; Y[i] = px[p*3+1]; Z[i] = px[p*3+2];
        D[i] = 1e10f;
    }
    __shared__ float s_val[NW], s_x[NW], s_y[NW], s_z[NW];
    __shared__ int   s_idx[NW];
    __shared__ float s_l[3];
    if (t == 0) {
        s_l[0] = px[0]; s_l[1] = px[1]; s_l[2] = px[2];
        out[0] = px[0]; out[1] = px[1]; out[2] = px[2];
    }
    __syncthreads();

    for (int j = 1; j < m; j++) {
        float lx = s_l[0], ly = s_l[1], lz = s_l[2];
        float bv = -1.f, bx = 0.f, by = 0.f, bz = 0.f;
        int bi = 0;
#pragma unroll
        for (int i = 0; i < NPT; i++) {
            float dx = X[i]-lx, dy = Y[i]-ly, dz = Z[i]-lz;
            float d  = fmaf(dx, dx, fmaf(dy, dy, dz*dz));
            float nd = fminf(D[i], d);
            D[i] = nd;
            if (nd > bv) { bv = nd; bi = t + i*NTH; bx = X[i]; by = Y[i]; bz = Z[i]; }
        }
#pragma unroll
        for (int o = 16; o > 0; o >>= 1) {
            float ov = __shfl_down_sync(0xffffffffu, bv, o);
            int   oi = __shfl_down_sync(0xffffffffu, bi, o);
            float ox = __shfl_down_sync(0xffffffffu, bx, o);
            float oy = __shfl_down_sync(0xffffffffu, by, o);
            float oz = __shfl_down_sync(0xffffffffu, bz, o);
            if (ov > bv || (ov == bv && oi < bi)) { bv=ov; bi=oi; bx=ox; by=oy; bz=oz; }
        }
        if (lane == 0) { s_val[w]=bv; s_idx[w]=bi; s_x[w]=bx; s_y[w]=by; s_z[w]=bz; }
        __syncthreads();
        if (w == 0) {
            float v  = (lane < NW) ? s_val[lane] : -2.f;
            int   ii = (lane < NW) ? s_idx[lane] : 0x7fffffff;
            int   sl = lane;
#pragma unroll
            for (int o = 16; o > 0; o >>= 1) {
                float ov = __shfl_down_sync(0xffffffffu, v,  o);
                int   oi = __shfl_down_sync(0xffffffffu, ii, o);
                int   os = __shfl_down_sync(0xffffffffu, sl, o);
                if (ov > v || (ov == v && oi < ii)) { v=ov; ii=oi; sl=os; }
            }
            if (lane == 0) {
                float nx = s_x[sl], ny = s_y[sl], nz = s_z[sl];
                s_l[0] = nx; s_l[1] = ny; s_l[2] = nz;
                out[j*3] = nx; out[j*3+1] = ny; out[j*3+2] = nz;
            }
        }
        __syncthreads();
    }
}

// ---------------- ball query, warp-per-centroid (no barriers) ----------------
// first-KN valid (d2 < r2) in index order; pad with first valid index.
template<int KN>
__global__ void k_ball_query_w(const float* __restrict__ xyz, const float* __restrict__ cent,
                               int n, int mPerB, int totalM, float r2, int* __restrict__ out) {
    int wg = blockIdx.x * (blockDim.x >> 5) + (threadIdx.x >> 5);
    if (wg >= totalM) return;
    int lane = threadIdx.x & 31;
    int b = wg / mPerB;
    const float* px = xyz + (size_t)b*n*3;
    const float* c  = cent + (size_t)wg*3;
    float cx = c[0], cy = c[1], cz = c[2];
    int* o = out + (size_t)wg*KN;

    int cnt = 0;
    int first = -1;
    for (int base = 0; base < n && cnt < KN; base += 32) {
        int p = base + lane;
        bool valid = false;
        if (p < n) {
            float dx = px[p*3]-cx, dy = px[p*3+1]-cy, dz = px[p*3+2]-cz;
            valid = fmaf(dx, dx, fmaf(dy, dy, dz*dz)) < r2;
        }
        unsigned bal = __ballot_sync(0xffffffffu, valid);
        if (first < 0 && bal) first = base + __ffs(bal) - 1;
        int prefix = __popc(bal & ((1u << lane) - 1));
        if (valid && cnt + prefix < KN) o[cnt + prefix] = p;
        cnt += __popc(bal);
    }
    // pad remainder with first valid index (cnt >= 1 always: centroid is a data point)
    int c0 = (cnt < KN) ? cnt : KN;
    for (int i = c0 + lane; i < KN; i += 32) o[i] = first;
}

// ---------------- grouping: write pre-split bf16 planes ----------------
// SA1: per sample row, 8 cols (3 diffs + 5 zero pad)
__global__ void k_group1(const float* __restrict__ xyz, const float* __restrict__ cent,
                         const int* __restrict__ idx,
                         __nv_bfloat16* __restrict__ Ahi, __nv_bfloat16* __restrict__ Alo) {
    int r = blockIdx.x * blockDim.x + threadIdx.x;
    if (r >= BATCH*SAM1*SAK1) return;
    int bm = r / SAK1;
    int b  = bm / SAM1;
    int i  = idx[r];
    const float* p = xyz + ((size_t)b*NPTS + i)*3;
    const float* c = cent + (size_t)bm*3;
    uint32_t h01, l01, h23, l23;
    split2(p[0]-c[0], p[1]-c[1], h01, l01);
    split2(p[2]-c[2], 0.f,       h23, l23);
    *(uint4*)&Ahi[(size_t)r*8] = make_uint4(h01, h23, 0, 0);
    *(uint4*)&Alo[(size_t)r*8] = make_uint4(l01, l23, 0, 0);
}

// SA2: per (sample row, 8-col group); 136 cols = 3 diffs + 128 feats + 5 pad
__global__ void k_group2(const float* __restrict__ xyz1, const float* __restrict__ cent2,
                         const int* __restrict__ idx,
                         const __nv_bfloat16* __restrict__ F1h, const __nv_bfloat16* __restrict__ F1l,
                         __nv_bfloat16* __restrict__ Ahi, __nv_bfloat16* __restrict__ Alo) {
    int e = blockIdx.x * blockDim.x + threadIdx.x;
    if (e >= BATCH*SAM2*SAK2*17) return;
    int g = e % 17;
    int r = e / 17;
    int bm = r / SAK2;
    int b  = bm / SAM2;
    int i  = idx[r];
    size_t frow = ((size_t)b*SAM1 + i)*128;
    uint32_t hw[4], lw[4];
#pragma unroll
    for (int q = 0; q < 4; q++) {
        float v0, v1;
        int c0 = g*8 + q*2, c1 = c0 + 1;
        if (c0 < 3)       v0 = xyz1[((size_t)b*SAM1 + i)*3 + c0] - cent2[(size_t)bm*3 + c0];
        else if (c0 < 131) v0 = __bfloat162float(F1h[frow + c0 - 3]) + __bfloat162float(F1l[frow + c0 - 3]);
        else              v0 = 0.f;
        if (c1 < 3)       v1 = xyz1[((size_t)b*SAM1 + i)*3 + c1] - cent2[(size_t)bm*3 + c1];
        else if (c1 < 131) v1 = __bfloat162float(F1h[frow + c1 - 3]) + __bfloat162float(F1l[frow + c1 - 3]);
        else              v1 = 0.f;
        split2(v0, v1, hw[q], lw[q]);
    }
    size_t o = (size_t)r*136 + g*8;
    *(uint4*)&Ahi[o] = make_uint4(hw[0], hw[1], hw[2], hw[3]);
    *(uint4*)&Alo[o] = make_uint4(lw[0], lw[1], lw[2], lw[3]);
}

// ---------------- fp32 GEMM for tiny M (glob/cls layers) ----------------
__global__ void k_relu_gemm(const float* __restrict__ A, const float* __restrict__ W,
                            const float* __restrict__ bias, float* __restrict__ C,
                            int M, int Nn, int K, int relu) {
    __shared__ float As[16][128];
    __shared__ float Ws[16][64];
    int m0 = blockIdx.x * 128;
    int n0 = blockIdx.y * 64;
    int tid = threadIdx.x;
    int tx = tid & 15;
    int ty = tid >> 4;
    float acc[8][4] = {};
    for (int k0 = 0; k0 < K; k0 += 16) {
#pragma unroll
        for (int r = 0; r < 8; r++) {
            int lin = tid + r*256;
            int mm = lin >> 4, kk = lin & 15;
            int gm = m0 + mm, gk = k0 + kk;
            As[kk][mm] = (gm < M && gk < K) ? A[(size_t)gm*K + gk] : 0.f;
        }
#pragma unroll
        for (int r = 0; r < 4; r++) {
            int lin = tid + r*256;
            int nn = lin >> 4, kk = lin & 15;
            int gn = n0 + nn, gk = k0 + kk;
            Ws[kk][nn] = (gn < Nn && gk < K) ? W[(size_t)gn*K + gk] : 0.f;
        }
        __syncthreads();
#pragma unroll
        for (int kk = 0; kk < 16; kk++) {
            float a[8], w[4];
#pragma unroll
            for (int i = 0; i < 8; i++) a[i] = As[kk][ty*8 + i];
#pragma unroll
            for (int j = 0; j < 4; j++) w[j] = Ws[kk][tx*4 + j];
#pragma unroll
            for (int i = 0; i < 8; i++)
#pragma unroll
                for (int j = 0; j < 4; j++)
                    acc[i][j] = fmaf(a[i], w[j], acc[i][j]);
        }
        __syncthreads();
    }
#pragma unroll
    for (int i = 0; i < 8; i++) {
        int gm = m0 + ty*8 + i;
        if (gm >= M) continue;
#pragma unroll
        for (int j = 0; j < 4; j++) {
            int gn = n0 + tx*4 + j;
            if (gn >= Nn) continue;
            float v = acc[i][j] + bias[gn];
            if (relu) v = fmaxf(v, 0.f);
            C[(size_t)gm*Nn + gn] = v;
        }
    }
}

extern "C" void kernel_launch(void* const* d_in, const int* in_sizes, int n_in,
                              void* d_out, int out_size) {
    const float* pts     = (const float*)d_in[0];
    const float* sa1_w0  = (const float*)d_in[1];  const float* sa1_b0 = (const float*)d_in[2];
    const float* sa1_w1  = (const float*)d_in[3];  const float* sa1_b1 = (const float*)d_in[4];
    const float* sa1_w2  = (const float*)d_in[5];  const float* sa1_b2 = (const float*)d_in[6];
    const float* sa2_w0  = (const float*)d_in[7];  const float* sa2_b0 = (const float*)d_in[8];
    const float* sa2_w1  = (const float*)d_in[9];  const float* sa2_b1 = (const float*)d_in[10];
    const float* sa2_w2  = (const float*)d_in[11]; const float* sa2_b2 = (const float*)d_in[12];
    const float* loc_w0  = (const float*)d_in[13]; const float* loc_b0 = (const float*)d_in[14];
    const float* loc_w1  = (const float*)d_in[15]; const float* loc_b1 = (const float*)d_in[16];
    const float* loc_w2  = (const float*)d_in[17]; const float* loc_b2 = (const float*)d_in[18];
    const float* glob_w0 = (const float*)d_in[19]; const float* glob_b0 = (const float*)d_in[20];
    const float* glob_w1 = (const float*)d_in[21]; const float* glob_b1 = (const float*)d_in[22];
    const float* cls_w   = (const float*)d_in[23]; const float* cls_b  = (const float*)d_in[24];
    float* out = (float*)d_out;

    float *xyz, *new1, *new2, *pool, *gl1, *gl2;
    int *idx1, *idx2;
    __nv_bfloat16 *INh, *INl, *P0h, *P0l, *P1h, *P1l, *F1h, *F1l, *F2h, *F2l, *Wh, *Wl;
    cudaGetSymbolAddress((void**)&xyz,  g_xyz);
    cudaGetSymbolAddress((void**)&new1, g_new1);
    cudaGetSymbolAddress((void**)&new2, g_new2);
    cudaGetSymbolAddress((void**)&idx1, g_idx1);
    cudaGetSymbolAddress((void**)&idx2, g_idx2);
    cudaGetSymbolAddress((void**)&pool, g_pool);
    cudaGetSymbolAddress((void**)&gl1,  g_gl1);
    cudaGetSymbolAddress((void**)&gl2,  g_gl2);
    cudaGetSymbolAddress((void**)&INh,  g_INh);  cudaGetSymbolAddress((void**)&INl, g_INl);
    cudaGetSymbolAddress((void**)&P0h,  g_P0h);  cudaGetSymbolAddress((void**)&P0l, g_P0l);
    cudaGetSymbolAddress((void**)&P1h,  g_P1h);  cudaGetSymbolAddress((void**)&P1l, g_P1l);
    cudaGetSymbolAddress((void**)&F1h,  g_F1h);  cudaGetSymbolAddress((void**)&F1l, g_F1l);
    cudaGetSymbolAddress((void**)&F2h,  g_F2h);  cudaGetSymbolAddress((void**)&F2l, g_F2l);
    cudaGetSymbolAddress((void**)&Wh,   g_Wh);   cudaGetSymbolAddress((void**)&Wl,  g_Wl);

    // weight plane offsets (elems)
    const int oW0 = 0,      oW1 = 512,    oW2 = 4608,   oW3 = 12800,  oW4 = 30208;
    const int oW5 = 46592,  oW6 = 79360,  oW7 = 144896, oW8 = 275968;
    struct { const float* w; int off, N, K, Kp; } WS[9] = {
        {sa1_w0, oW0,   64,   3,   8}, {sa1_w1, oW1,   64,  64,  64}, {sa1_w2, oW2,  128,  64,  64},
        {sa2_w0, oW3,  128, 131, 136}, {sa2_w1, oW4,  128, 128, 128}, {sa2_w2, oW5,  256, 128, 128},
        {loc_w0, oW6,  256, 256, 256}, {loc_w1, oW7,  512, 256, 256}, {loc_w2, oW8, 1024, 512, 512},
    };
    for (int i = 0; i < 9; i++)
        k_wsplit<<<(WS[i].N*WS[i].Kp + 255)/256, 256>>>(WS[i].w, Wh + WS[i].off, Wl + WS[i].off,
                                                        WS[i].N, WS[i].K, WS[i].Kp);

    // transpose points -> xyz [B,N,3]
    k_transpose<<<(BATCH*3*NPTS + 255)/256, 256>>>(pts, xyz);

    // ---- SA1 ----
    k_fps<8, 1024><<<BATCH, 1024>>>(xyz, new1, NPTS, SAM1);
    {
        const int totalM = BATCH*SAM1;          // 16384 warps, 8/block
        k_ball_query_w<SAK1><<<(totalM + 7)/8, 256>>>(xyz, new1, NPTS, SAM1, totalM, 0.2f*0.2f, idx1);
    }
    k_group1<<<(BATCH*SAM1*SAK1 + 255)/256, 256>>>(xyz, new1, idx1, INh, INl);
    {
        const int M = BATCH*SAM1*SAK1;          // 524288
        k_wmma<<<dim3(M/128, 1), 256>>>(INh, INl, Wh+oW0, Wl+oW0, sa1_b0, nullptr, P0h, P0l, M,  64,   8,  0, 0);
        k_wmma<<<dim3(M/128, 1), 256>>>(P0h, P0l, Wh+oW1, Wl+oW1, sa1_b1, nullptr, P1h, P1l, M,  64,  64,  0, 0);
        k_wmma<<<dim3(M/128, 2), 256>>>(P1h, P1l, Wh+oW2, Wl+oW2, sa1_b2, nullptr, F1h, F1l, M, 128,  64, 32, 0);
    }

    // ---- SA2 ----
    k_fps<1, 512><<<BATCH, 512>>>(new1, new2, SAM1, SAM2);
    {
        const int totalM = BATCH*SAM2;          // 4096 warps
        k_ball_query_w<SAK2><<<(totalM + 7)/8, 256>>>(new1, new2, SAM1, SAM2, totalM, 0.4f*0.4f, idx2);
    }
    {
        int tot = BATCH*SAM2*SAK2*17;
        k_group2<<<(tot + 255)/256, 256>>>(new1, new2, idx2, F1h, F1l, INh, INl);
        const int M = BATCH*SAM2*SAK2;          // 262144
        k_wmma<<<dim3(M/128, 2), 256>>>(INh, INl, Wh+oW3, Wl+oW3, sa2_b0, nullptr, P0h, P0l, M, 128, 136,  0, 0);
        k_wmma<<<dim3(M/128, 2), 256>>>(P0h, P0l, Wh+oW4, Wl+oW4, sa2_b1, nullptr, P1h, P1l, M, 128, 128,  0, 0);
        k_wmma<<<dim3(M/128, 4), 256>>>(P1h, P1l, Wh+oW5, Wl+oW5, sa2_b2, nullptr, F2h, F2l, M, 256, 128, 64, 0);
    }

    // ---- local MLP + fused global max-pool ----
    {
        const int M = BATCH*SAM2;               // 4096
        k_wmma<<<dim3(M/128,  4), 256>>>(F2h, F2l, Wh+oW6, Wl+oW6, loc_b0, nullptr, P0h, P0l, M,  256, 256,   0, 0);
        k_wmma<<<dim3(M/128,  8), 256>>>(P0h, P0l, Wh+oW7, Wl+oW7, loc_b1, nullptr, P1h, P1l, M,  512, 256,   0, 0);
        k_wmma<<<dim3(M/128, 16), 256>>>(P1h, P1l, Wh+oW8, Wl+oW8, loc_b2, pool, nullptr, nullptr, M, 1024, 512, 128, 1);
    }

    // ---- global MLP + classifier (tiny M=32, fp32 path) ----
    {
        dim3 g1(1, 8);  k_relu_gemm<<<g1, 256>>>(pool, glob_w0, glob_b0, gl1, BATCH, 512, 1024, 1);
        dim3 g2(1, 4);  k_relu_gemm<<<g2, 256>>>(gl1,  glob_w1, glob_b1, gl2, BATCH, 256,  512, 1);
        dim3 g3(1, 1);  k_relu_gemm<<<g3, 256>>>(gl2,  cls_w,   cls_b,   out, BATCH,  40,  256, 0);
    }
}

// round 16
// speedup vs baseline: 1.5551x; 1.5551x over previous
#include <cuda_runtime.h>
#include <cuda_bf16.h>
#include <math.h>
#include <stdint.h>

#define BATCH 32
#define NPTS  8192
#define SAM1  512
#define SAK1  32
#define SAM2  128
#define SAK2  64

// ---------------- static scratch (no runtime allocation) ----------------
__device__ float g_xyz [BATCH*NPTS*3];
__device__ float g_new1[BATCH*SAM1*3];
__device__ float g_new2[BATCH*SAM2*3];
__device__ int   g_idx1[BATCH*SAM1*SAK1];
__device__ int   g_idx2[BATCH*SAM2*SAK2];
__device__ float g_pool[BATCH*1024];
__device__ float g_gl1 [BATCH*512];
__device__ float g_gl2 [BATCH*256];
// bf16 hi/lo activation planes
__device__ __align__(16) __nv_bfloat16 g_INh[35651584], g_INl[35651584]; // 262144x136 max
__device__ __align__(16) __nv_bfloat16 g_P0h[33554432], g_P0l[33554432]; // 524288x64 max
__device__ __align__(16) __nv_bfloat16 g_P1h[33554432], g_P1l[33554432];
__device__ __align__(16) __nv_bfloat16 g_F1h[2097152],  g_F1l[2097152];  // 16384x128
__device__ __align__(16) __nv_bfloat16 g_F2h[1048576],  g_F2l[1048576];  // 4096x256
__device__ __align__(16) __nv_bfloat16 g_Wh [1048576],  g_Wl [1048576];  // all weights

__device__ __forceinline__ uint32_t smem_u32(const void* p) {
    uint32_t a;
    asm("{ .reg .u64 t; cvta.to.shared.u64 t, %1; cvt.u32.u64 %0, t; }" : "=r"(a) : "l"(p));
    return a;
}
__device__ __forceinline__ void split1(float v, __nv_bfloat16& h, __nv_bfloat16& l) {
    h = __float2bfloat16(v);
    l = __float2bfloat16(v - __bfloat162float(h));
}
__device__ __forceinline__ void split2(float a, float b, uint32_t& hi, uint32_t& lo) {
    __nv_bfloat16 ha, la, hb, lb;
    split1(a, ha, la); split1(b, hb, lb);
    hi = ((uint32_t)__bfloat16_as_ushort(hb) << 16) | __bfloat16_as_ushort(ha);
    lo = ((uint32_t)__bfloat16_as_ushort(lb) << 16) | __bfloat16_as_ushort(la);
}
__device__ __forceinline__ void ldm_x4(uint32_t* r, uint32_t addr) {
    asm volatile("ldmatrix.sync.aligned.m8n8.x4.shared.b16 {%0,%1,%2,%3}, [%4];"
                 : "=r"(r[0]), "=r"(r[1]), "=r"(r[2]), "=r"(r[3]) : "r"(addr));
}
__device__ __forceinline__ void ldm_x2(uint32_t* r, uint32_t addr) {
    asm volatile("ldmatrix.sync.aligned.m8n8.x2.shared.b16 {%0,%1}, [%2];"
                 : "=r"(r[0]), "=r"(r[1]) : "r"(addr));
}
__device__ __forceinline__ void mma16816(float* c, const uint32_t* a, const uint32_t* b) {
    asm volatile(
        "mma.sync.aligned.m16n8k16.row.col.f32.bf16.bf16.f32 "
        "{%0,%1,%2,%3}, {%4,%5,%6,%7}, {%8,%9}, {%0,%1,%2,%3};"
        : "+f"(c[0]), "+f"(c[1]), "+f"(c[2]), "+f"(c[3])
        : "r"(a[0]), "r"(a[1]), "r"(a[2]), "r"(a[3]), "r"(b[0]), "r"(b[1]));
}

// =====================================================================
// warp-MMA GEMM on pre-split bf16 planes, register-staged pipeline.
// C[M,N] = relu(A @ W^T + bias); A row stride Ks (=Kpad, mult of 8).
// Tile 128x64, BK=32, 256 threads (8 warps 4x2), 3-term hi/lo split.
// Prefetch chunk ck+1 G->R after the post-store barrier so LDG latency
// overlaps the MMA phase of chunk ck.
// poolk>0: fused max over poolk-row groups. fp32out: fp32 to outF,
// else bf16 hi/lo planes (row stride N).
// =====================================================================
__global__ void __launch_bounds__(256)
k_wmma(const __nv_bfloat16* __restrict__ Ahi, const __nv_bfloat16* __restrict__ Alo,
       const __nv_bfloat16* __restrict__ Whi, const __nv_bfloat16* __restrict__ Wlo,
       const float* __restrict__ bias, float* __restrict__ outF,
       __nv_bfloat16* __restrict__ outHi, __nv_bfloat16* __restrict__ outLo,
       int M, int N, int Ks, int poolk, int fp32out) {
    constexpr int STR = 40;                       // bf16 row stride (80B)
    __shared__ __align__(16) char sraw[34816];
    __shared__ float sbias[64];
    __nv_bfloat16 (*Ah)[STR] = reinterpret_cast<__nv_bfloat16(*)[STR]>(sraw);
    __nv_bfloat16 (*Al)[STR] = reinterpret_cast<__nv_bfloat16(*)[STR]>(sraw + 10240);
    __nv_bfloat16 (*Bh)[STR] = reinterpret_cast<__nv_bfloat16(*)[STR]>(sraw + 20480);
    __nv_bfloat16 (*Bl)[STR] = reinterpret_cast<__nv_bfloat16(*)[STR]>(sraw + 25600);
    float (*epi)[68] = reinterpret_cast<float(*)[68]>(sraw);

    const int tid = threadIdx.x, lane = tid & 31, wid = tid >> 5;
    const int wm = wid & 3, wn = wid >> 2;
    const int m0 = blockIdx.x * 128, n0 = blockIdx.y * 64;

    if (tid < 64) sbias[tid] = (n0 + tid < N) ? bias[n0 + tid] : 0.f;

    float acc[2][4][4];
#pragma unroll
    for (int mt = 0; mt < 2; mt++)
#pragma unroll
        for (int nt = 0; nt < 4; nt++)
#pragma unroll
            for (int v = 0; v < 4; v++) acc[mt][nt][v] = 0.f;

    const uint4 z4 = make_uint4(0, 0, 0, 0);
    const int nchunks = (Ks + 31) >> 5;
    const int ar0 = tid >> 2, ag = (tid & 3) * 8;
    const int br  = tid >> 2, bg = (tid & 3) * 8;

    uint4 a_h[2], a_l[2], b_h, b_l;
    {   // prefetch chunk 0
#pragma unroll
        for (int j = 0; j < 2; j++) {
            int r = ar0 + j*64;
            int gm = m0 + r, gk = ag;
            a_h[j] = z4; a_l[j] = z4;
            if (gm < M && gk < Ks) {
                size_t o = (size_t)gm*Ks + gk;
                a_h[j] = *(const uint4*)&Ahi[o];
                a_l[j] = *(const uint4*)&Alo[o];
            }
        }
        int gn = n0 + br, gk = bg;
        b_h = z4; b_l = z4;
        if (gn < N && gk < Ks) {
            size_t o = (size_t)gn*Ks + gk;
            b_h = *(const uint4*)&Whi[o];
            b_l = *(const uint4*)&Wlo[o];
        }
    }

    for (int ck = 0; ck < nchunks; ck++) {
#pragma unroll
        for (int j = 0; j < 2; j++) {
            int r = ar0 + j*64;
            *(uint4*)&Ah[r][ag] = a_h[j];
            *(uint4*)&Al[r][ag] = a_l[j];
        }
        *(uint4*)&Bh[br][bg] = b_h;
        *(uint4*)&Bl[br][bg] = b_l;
        __syncthreads();

        if (ck + 1 < nchunks) {
            const int kb = (ck + 1) << 5;
#pragma unroll
            for (int j = 0; j < 2; j++) {
                int r = ar0 + j*64;
                int gm = m0 + r, gk = kb + ag;
                a_h[j] = z4; a_l[j] = z4;
                if (gm < M && gk < Ks) {
                    size_t o = (size_t)gm*Ks + gk;
                    a_h[j] = *(const uint4*)&Ahi[o];
                    a_l[j] = *(const uint4*)&Alo[o];
                }
            }
            int gn = n0 + br, gk = kb + bg;
            b_h = z4; b_l = z4;
            if (gn < N && gk < Ks) {
                size_t o = (size_t)gn*Ks + gk;
                b_h = *(const uint4*)&Whi[o];
                b_l = *(const uint4*)&Wlo[o];
            }
        }

#pragma unroll
        for (int ks = 0; ks < 32; ks += 16) {
            uint32_t ah[2][4], al[2][4];
#pragma unroll
            for (int mt = 0; mt < 2; mt++) {
                int row = wm*32 + mt*16 + (lane & 7) + ((lane >> 3) & 1)*8;
                int kc  = ks + (lane >> 4)*8;
                ldm_x4(ah[mt], smem_u32(&Ah[row][kc]));
                ldm_x4(al[mt], smem_u32(&Al[row][kc]));
            }
            uint32_t bh[4][2], bl[4][2];
#pragma unroll
            for (int nt = 0; nt < 4; nt++) {
                int nr = wn*32 + nt*8 + (lane & 7);
                int kc = ks + ((lane >> 3) & 1)*8;
                ldm_x2(bh[nt], smem_u32(&Bh[nr][kc]));
                ldm_x2(bl[nt], smem_u32(&Bl[nr][kc]));
            }
#pragma unroll
            for (int mt = 0; mt < 2; mt++)
#pragma unroll
                for (int nt = 0; nt < 4; nt++) {
                    mma16816(acc[mt][nt], ah[mt], bh[nt]);
                    mma16816(acc[mt][nt], ah[mt], bl[nt]);
                    mma16816(acc[mt][nt], al[mt], bh[nt]);
                }
        }
        __syncthreads();
    }

    // ---- epilogue: bias + relu -> padded smem ----
    {
        int gid = lane >> 2, tig = lane & 3;
#pragma unroll
        for (int mt = 0; mt < 2; mt++)
#pragma unroll
            for (int nt = 0; nt < 4; nt++) {
                int r0 = wm*32 + mt*16 + gid;
                int cc = wn*32 + nt*8 + tig*2;
                epi[r0    ][cc    ] = fmaxf(acc[mt][nt][0] + sbias[cc    ], 0.f);
                epi[r0    ][cc + 1] = fmaxf(acc[mt][nt][1] + sbias[cc + 1], 0.f);
                epi[r0 + 8][cc    ] = fmaxf(acc[mt][nt][2] + sbias[cc    ], 0.f);
                epi[r0 + 8][cc + 1] = fmaxf(acc[mt][nt][3] + sbias[cc + 1], 0.f);
            }
    }
    __syncthreads();

    if (poolk == 0) {
#pragma unroll
        for (int j = 0; j < 4; j++) {
            int i = tid + j*256;
            int r = i >> 3, g = i & 7;
            int gm = m0 + r;
            if (gm < M) {
                const float* e = &epi[r][g*8];
                uint32_t h0,l0,h1,l1,h2,l2,h3,l3;
                split2(e[0], e[1], h0, l0);
                split2(e[2], e[3], h1, l1);
                split2(e[4], e[5], h2, l2);
                split2(e[6], e[7], h3, l3);
                size_t o = (size_t)gm*N + n0 + g*8;
                *(uint4*)&outHi[o] = make_uint4(h0, h1, h2, h3);
                *(uint4*)&outLo[o] = make_uint4(l0, l1, l2, l3);
            }
        }
    } else {
        int ng = 128 / poolk;
        for (int idx = tid; idx < 64*ng; idx += 256) {
            int c = idx & 63, g = idx >> 6;
            float mv = epi[g*poolk][c];
            for (int r = 1; r < poolk; r++) mv = fmaxf(mv, epi[g*poolk + r][c]);
            size_t o = (size_t)(m0/poolk + g)*N + n0 + c;
            if (fp32out) {
                outF[o] = mv;
            } else {
                __nv_bfloat16 h, l;
                split1(mv, h, l);
                outHi[o] = h; outLo[o] = l;
            }
        }
    }
}

// ---------------- merged weight split: all 9 layers in one launch ----------------
#define WSPLIT_TOT 800256
__global__ void k_wsplit_all(const float* __restrict__ w0, const float* __restrict__ w1,
                             const float* __restrict__ w2, const float* __restrict__ w3,
                             const float* __restrict__ w4, const float* __restrict__ w5,
                             const float* __restrict__ w6, const float* __restrict__ w7,
                             const float* __restrict__ w8,
                             __nv_bfloat16* __restrict__ hi, __nv_bfloat16* __restrict__ lo) {
    int i = blockIdx.x * blockDim.x + threadIdx.x;
    if (i >= WSPLIT_TOT) return;
    const int ends[9]  = {512, 4608, 12800, 30208, 46592, 79360, 144896, 275968, 800256};
    const int Karr[9]  = {3, 64, 64, 131, 128, 128, 256, 256, 512};
    const int Kparr[9] = {8, 64, 64, 136, 128, 128, 256, 256, 512};
    const float* ws[9] = {w0, w1, w2, w3, w4, w5, w6, w7, w8};
    int s = 0;
    while (i >= ends[s]) s++;
    int start = (s == 0) ? 0 : ends[s-1];
    int local = i - start;
    int Kp = Kparr[s], K = Karr[s];
    int n = local / Kp, c = local - n*Kp;
    float v = (c < K) ? ws[s][(size_t)n*K + c] : 0.f;
    __nv_bfloat16 h, l;
    split1(v, h, l);
    hi[i] = h; lo[i] = l;
}

// ---------------- transpose [B,3,N] -> [B,N,3] ----------------
__global__ void k_transpose(const float* __restrict__ pts, float* __restrict__ xyz) {
    int i = blockIdx.x * blockDim.x + threadIdx.x;
    if (i >= BATCH*3*NPTS) return;
    int b = i / (3*NPTS);
    int r = i - b*3*NPTS;
    int c = r / NPTS;
    int n = r - c*NPTS;
    xyz[((size_t)b*NPTS + n)*3 + c] = pts[i];
}

// ---------------- farthest point sampling ----------------
template<int NPT, int NTH>
__global__ void k_fps(const float* __restrict__ xyz, float* __restrict__ out_xyz,
                      int n, int m) {
    constexpr int NW = NTH/32;
    int b = blockIdx.x;
    const float* px = xyz + (size_t)b*n*3;
    float* out = out_xyz + (size_t)b*m*3;
    int t = threadIdx.x, lane = t & 31, w = t >> 5;

    float X[NPT], Y[NPT], Z[NPT], D[NPT];
#pragma unroll
    for (int i = 0; i < NPT; i++) {
        int p = t + i*NTH;
        X[i] = px[p*3]; Y[i] = px[p*3+1]; Z[i] = px[p*3+2];
        D[i] = 1e10f;
    }
    __shared__ float s_val[NW], s_x[NW], s_y[NW], s_z[NW];
    __shared__ int   s_idx[NW];
    __shared__ float s_l[3];
    if (t == 0) {
        s_l[0] = px[0]; s_l[1] = px[1]; s_l[2] = px[2];
        out[0] = px[0]; out[1] = px[1]; out[2] = px[2];
    }
    __syncthreads();

    for (int j = 1; j < m; j++) {
        float lx = s_l[0], ly = s_l[1], lz = s_l[2];
        float bv = -1.f, bx = 0.f, by = 0.f, bz = 0.f;
        int bi = 0;
#pragma unroll
        for (int i = 0; i < NPT; i++) {
            float dx = X[i]-lx, dy = Y[i]-ly, dz = Z[i]-lz;
            float d  = fmaf(dx, dx, fmaf(dy, dy, dz*dz));
            float nd = fminf(D[i], d);
            D[i] = nd;
            if (nd > bv) { bv = nd; bi = t + i*NTH; bx = X[i]; by = Y[i]; bz = Z[i]; }
        }
#pragma unroll
        for (int o = 16; o > 0; o >>= 1) {
            float ov = __shfl_down_sync(0xffffffffu, bv, o);
            int   oi = __shfl_down_sync(0xffffffffu, bi, o);
            float ox = __shfl_down_sync(0xffffffffu, bx, o);
            float oy = __shfl_down_sync(0xffffffffu, by, o);
            float oz = __shfl_down_sync(0xffffffffu, bz, o);
            if (ov > bv || (ov == bv && oi < bi)) { bv=ov; bi=oi; bx=ox; by=oy; bz=oz; }
        }
        if (lane == 0) { s_val[w]=bv; s_idx[w]=bi; s_x[w]=bx; s_y[w]=by; s_z[w]=bz; }
        __syncthreads();
        if (w == 0) {
            float v  = (lane < NW) ? s_val[lane] : -2.f;
            int   ii = (lane < NW) ? s_idx[lane] : 0x7fffffff;
            int   sl = lane;
#pragma unroll
            for (int o = 16; o > 0; o >>= 1) {
                float ov = __shfl_down_sync(0xffffffffu, v,  o);
                int   oi = __shfl_down_sync(0xffffffffu, ii, o);
                int   os = __shfl_down_sync(0xffffffffu, sl, o);
                if (ov > v || (ov == v && oi < ii)) { v=ov; ii=oi; sl=os; }
            }
            if (lane == 0) {
                float nx = s_x[sl], ny = s_y[sl], nz = s_z[sl];
                s_l[0] = nx; s_l[1] = ny; s_l[2] = nz;
                out[j*3] = nx; out[j*3+1] = ny; out[j*3+2] = nz;
            }
        }
        __syncthreads();
    }
}

// ---------------- ball query (block version, R9-proven) ----------------
template<int KN>
__global__ void k_ball_query(const float* __restrict__ xyz, const float* __restrict__ cent,
                             int n, int mPerB, float r2, int* __restrict__ out) {
    int bm = blockIdx.x;
    int b  = bm / mPerB;
    const float* px = xyz + (size_t)b*n*3;
    const float* c  = cent + (size_t)bm*3;
    float cx = c[0], cy = c[1], cz = c[2];
    __shared__ int s_idx[KN];
    __shared__ int s_cnt;
    __shared__ unsigned s_bal[4];
    if (threadIdx.x == 0) s_cnt = 0;
    __syncthreads();
    int t = threadIdx.x, lane = t & 31, w = t >> 5;
    for (int base = 0; base < n; base += 128) {
        int p = base + t;
        bool valid = false;
        if (p < n) {
            float dx = px[p*3]-cx, dy = px[p*3+1]-cy, dz = px[p*3+2]-cz;
            valid = (dx*dx + dy*dy + dz*dz) < r2;
        }
        unsigned bal = __ballot_sync(0xffffffffu, valid);
        if (lane == 0) s_bal[w] = bal;
        __syncthreads();
        if (t == 0) {
            int cnt = s_cnt;
            for (int ww = 0; ww < 4 && cnt < KN; ww++) {
                unsigned bb = s_bal[ww];
                while (bb && cnt < KN) {
                    int l = __ffs(bb) - 1;
                    s_idx[cnt++] = base + ww*32 + l;
                    bb &= bb - 1;
                }
            }
            s_cnt = cnt;
        }
        __syncthreads();
        if (s_cnt >= KN) break;
    }
    int cnt = s_cnt;
    if (t < KN) out[(size_t)bm*KN + t] = (t < cnt) ? s_idx[t] : s_idx[0];
}

// ---------------- grouping: write pre-split bf16 planes ----------------
__global__ void k_group1(const float* __restrict__ xyz, const float* __restrict__ cent,
                         const int* __restrict__ idx,
                         __nv_bfloat16* __restrict__ Ahi, __nv_bfloat16* __restrict__ Alo) {
    int r = blockIdx.x * blockDim.x + threadIdx.x;
    if (r >= BATCH*SAM1*SAK1) return;
    int bm = r / SAK1;
    int b  = bm / SAM1;
    int i  = idx[r];
    const float* p = xyz + ((size_t)b*NPTS + i)*3;
    const float* c = cent + (size_t)bm*3;
    uint32_t h01, l01, h23, l23;
    split2(p[0]-c[0], p[1]-c[1], h01, l01);
    split2(p[2]-c[2], 0.f,       h23, l23);
    *(uint4*)&Ahi[(size_t)r*8] = make_uint4(h01, h23, 0, 0);
    *(uint4*)&Alo[(size_t)r*8] = make_uint4(l01, l23, 0, 0);
}

__global__ void k_group2(const float* __restrict__ xyz1, const float* __restrict__ cent2,
                         const int* __restrict__ idx,
                         const __nv_bfloat16* __restrict__ F1h, const __nv_bfloat16* __restrict__ F1l,
                         __nv_bfloat16* __restrict__ Ahi, __nv_bfloat16* __restrict__ Alo) {
    int e = blockIdx.x * blockDim.x + threadIdx.x;
    if (e >= BATCH*SAM2*SAK2*17) return;
    int g = e % 17;
    int r = e / 17;
    int bm = r / SAK2;
    int b  = bm / SAM2;
    int i  = idx[r];
    size_t frow = ((size_t)b*SAM1 + i)*128;
    uint32_t hw[4], lw[4];
#pragma unroll
    for (int q = 0; q < 4; q++) {
        float v0, v1;
        int c0 = g*8 + q*2, c1 = c0 + 1;
        if (c0 < 3)       v0 = xyz1[((size_t)b*SAM1 + i)*3 + c0] - cent2[(size_t)bm*3 + c0];
        else if (c0 < 131) v0 = __bfloat162float(F1h[frow + c0 - 3]) + __bfloat162float(F1l[frow + c0 - 3]);
        else              v0 = 0.f;
        if (c1 < 3)       v1 = xyz1[((size_t)b*SAM1 + i)*3 + c1] - cent2[(size_t)bm*3 + c1];
        else if (c1 < 131) v1 = __bfloat162float(F1h[frow + c1 - 3]) + __bfloat162float(F1l[frow + c1 - 3]);
        else              v1 = 0.f;
        split2(v0, v1, hw[q], lw[q]);
    }
    size_t o = (size_t)r*136 + g*8;
    *(uint4*)&Ahi[o] = make_uint4(hw[0], hw[1], hw[2], hw[3]);
    *(uint4*)&Alo[o] = make_uint4(lw[0], lw[1], lw[2], lw[3]);
}

// ---------------- fp32 GEMM for tiny M (glob/cls layers) ----------------
__global__ void k_relu_gemm(const float* __restrict__ A, const float* __restrict__ W,
                            const float* __restrict__ bias, float* __restrict__ C,
                            int M, int Nn, int K, int relu) {
    __shared__ float As[16][128];
    __shared__ float Ws[16][64];
    int m0 = blockIdx.x * 128;
    int n0 = blockIdx.y * 64;
    int tid = threadIdx.x;
    int tx = tid & 15;
    int ty = tid >> 4;
    float acc[8][4] = {};
    for (int k0 = 0; k0 < K; k0 += 16) {
#pragma unroll
        for (int r = 0; r < 8; r++) {
            int lin = tid + r*256;
            int mm = lin >> 4, kk = lin & 15;
            int gm = m0 + mm, gk = k0 + kk;
            As[kk][mm] = (gm < M && gk < K) ? A[(size_t)gm*K + gk] : 0.f;
        }
#pragma unroll
        for (int r = 0; r < 4; r++) {
            int lin = tid + r*256;
            int nn = lin >> 4, kk = lin & 15;
            int gn = n0 + nn, gk = k0 + kk;
            Ws[kk][nn] = (gn < Nn && gk < K) ? W[(size_t)gn*K + gk] : 0.f;
        }
        __syncthreads();
#pragma unroll
        for (int kk = 0; kk < 16; kk++) {
            float a[8], w[4];
#pragma unroll
            for (int i = 0; i < 8; i++) a[i] = As[kk][ty*8 + i];
#pragma unroll
            for (int j = 0; j < 4; j++) w[j] = Ws[kk][tx*4 + j];
#pragma unroll
            for (int i = 0; i < 8; i++)
#pragma unroll
                for (int j = 0; j < 4; j++)
                    acc[i][j] = fmaf(a[i], w[j], acc[i][j]);
        }
        __syncthreads();
    }
#pragma unroll
    for (int i = 0; i < 8; i++) {
        int gm = m0 + ty*8 + i;
        if (gm >= M) continue;
#pragma unroll
        for (int j = 0; j < 4; j++) {
            int gn = n0 + tx*4 + j;
            if (gn >= Nn) continue;
            float v = acc[i][j] + bias[gn];
            if (relu) v = fmaxf(v, 0.f);
            C[(size_t)gm*Nn + gn] = v;
        }
    }
}

extern "C" void kernel_launch(void* const* d_in, const int* in_sizes, int n_in,
                              void* d_out, int out_size) {
    const float* pts     = (const float*)d_in[0];
    const float* sa1_w0  = (const float*)d_in[1];  const float* sa1_b0 = (const float*)d_in[2];
    const float* sa1_w1  = (const float*)d_in[3];  const float* sa1_b1 = (const float*)d_in[4];
    const float* sa1_w2  = (const float*)d_in[5];  const float* sa1_b2 = (const float*)d_in[6];
    const float* sa2_w0  = (const float*)d_in[7];  const float* sa2_b0 = (const float*)d_in[8];
    const float* sa2_w1  = (const float*)d_in[9];  const float* sa2_b1 = (const float*)d_in[10];
    const float* sa2_w2  = (const float*)d_in[11]; const float* sa2_b2 = (const float*)d_in[12];
    const float* loc_w0  = (const float*)d_in[13]; const float* loc_b0 = (const float*)d_in[14];
    const float* loc_w1  = (const float*)d_in[15]; const float* loc_b1 = (const float*)d_in[16];
    const float* loc_w2  = (const float*)d_in[17]; const float* loc_b2 = (const float*)d_in[18];
    const float* glob_w0 = (const float*)d_in[19]; const float* glob_b0 = (const float*)d_in[20];
    const float* glob_w1 = (const float*)d_in[21]; const float* glob_b1 = (const float*)d_in[22];
    const float* cls_w   = (const float*)d_in[23]; const float* cls_b  = (const float*)d_in[24];
    float* out = (float*)d_out;

    float *xyz, *new1, *new2, *pool, *gl1, *gl2;
    int *idx1, *idx2;
    __nv_bfloat16 *INh, *INl, *P0h, *P0l, *P1h, *P1l, *F1h, *F1l, *F2h, *F2l, *Wh, *Wl;
    cudaGetSymbolAddress((void**)&xyz,  g_xyz);
    cudaGetSymbolAddress((void**)&new1, g_new1);
    cudaGetSymbolAddress((void**)&new2, g_new2);
    cudaGetSymbolAddress((void**)&idx1, g_idx1);
    cudaGetSymbolAddress((void**)&idx2, g_idx2);
    cudaGetSymbolAddress((void**)&pool, g_pool);
    cudaGetSymbolAddress((void**)&gl1,  g_gl1);
    cudaGetSymbolAddress((void**)&gl2,  g_gl2);
    cudaGetSymbolAddress((void**)&INh,  g_INh);  cudaGetSymbolAddress((void**)&INl, g_INl);
    cudaGetSymbolAddress((void**)&P0h,  g_P0h);  cudaGetSymbolAddress((void**)&P0l, g_P0l);
    cudaGetSymbolAddress((void**)&P1h,  g_P1h);  cudaGetSymbolAddress((void**)&P1l, g_P1l);
    cudaGetSymbolAddress((void**)&F1h,  g_F1h);  cudaGetSymbolAddress((void**)&F1l, g_F1l);
    cudaGetSymbolAddress((void**)&F2h,  g_F2h);  cudaGetSymbolAddress((void**)&F2l, g_F2l);
    cudaGetSymbolAddress((void**)&Wh,   g_Wh);   cudaGetSymbolAddress((void**)&Wl,  g_Wl);

    // weight plane offsets (elems; consecutive segments, see k_wsplit_all)
    const int oW0 = 0,      oW1 = 512,    oW2 = 4608,   oW3 = 12800,  oW4 = 30208;
    const int oW5 = 46592,  oW6 = 79360,  oW7 = 144896, oW8 = 275968;
    k_wsplit_all<<<(WSPLIT_TOT + 255)/256, 256>>>(sa1_w0, sa1_w1, sa1_w2, sa2_w0, sa2_w1,
                                                  sa2_w2, loc_w0, loc_w1, loc_w2, Wh, Wl);

    // transpose points -> xyz [B,N,3]
    k_transpose<<<(BATCH*3*NPTS + 255)/256, 256>>>(pts, xyz);

    // ---- SA1 ----
    k_fps<8, 1024><<<BATCH, 1024>>>(xyz, new1, NPTS, SAM1);
    k_ball_query<SAK1><<<BATCH*SAM1, 128>>>(xyz, new1, NPTS, SAM1, 0.2f*0.2f, idx1);
    k_group1<<<(BATCH*SAM1*SAK1 + 255)/256, 256>>>(xyz, new1, idx1, INh, INl);
    {
        const int M = BATCH*SAM1*SAK1;          // 524288
        k_wmma<<<dim3(M/128, 1), 256>>>(INh, INl, Wh+oW0, Wl+oW0, sa1_b0, nullptr, P0h, P0l, M,  64,   8,  0, 0);
        k_wmma<<<dim3(M/128, 1), 256>>>(P0h, P0l, Wh+oW1, Wl+oW1, sa1_b1, nullptr, P1h, P1l, M,  64,  64,  0, 0);
        k_wmma<<<dim3(M/128, 2), 256>>>(P1h, P1l, Wh+oW2, Wl+oW2, sa1_b2, nullptr, F1h, F1l, M, 128,  64, 32, 0);
    }

    // ---- SA2 ----
    k_fps<1, 512><<<BATCH, 512>>>(new1, new2, SAM1, SAM2);
    k_ball_query<SAK2><<<BATCH*SAM2, 128>>>(new1, new2, SAM1, SAM2, 0.4f*0.4f, idx2);
    {
        int tot = BATCH*SAM2*SAK2*17;
        k_group2<<<(tot + 255)/256, 256>>>(new1, new2, idx2, F1h, F1l, INh, INl);
        const int M = BATCH*SAM2*SAK2;          // 262144
        k_wmma<<<dim3(M/128, 2), 256>>>(INh, INl, Wh+oW3, Wl+oW3, sa2_b0, nullptr, P0h, P0l, M, 128, 136,  0, 0);
        k_wmma<<<dim3(M/128, 2), 256>>>(P0h, P0l, Wh+oW4, Wl+oW4, sa2_b1, nullptr, P1h, P1l, M, 128, 128,  0, 0);
        k_wmma<<<dim3(M/128, 4), 256>>>(P1h, P1l, Wh+oW5, Wl+oW5, sa2_b2, nullptr, F2h, F2l, M, 256, 128, 64, 0);
    }

    // ---- local MLP + fused global max-pool ----
    {
        const int M = BATCH*SAM2;               // 4096
        k_wmma<<<dim3(M/128,  4), 256>>>(F2h, F2l, Wh+oW6, Wl+oW6, loc_b0, nullptr, P0h, P0l, M,  256, 256,   0, 0);
        k_wmma<<<dim3(M/128,  8), 256>>>(P0h, P0l, Wh+oW7, Wl+oW7, loc_b1, nullptr, P1h, P1l, M,  512, 256,   0, 0);
        k_wmma<<<dim3(M/128, 16), 256>>>(P1h, P1l, Wh+oW8, Wl+oW8, loc_b2, pool, nullptr, nullptr, M, 1024, 512, 128, 1);
    }

    // ---- global MLP + classifier (tiny M=32, fp32 path) ----
    {
        dim3 g1(1, 8);  k_relu_gemm<<<g1, 256>>>(pool, glob_w0, glob_b0, gl1, BATCH, 512, 1024, 1);
        dim3 g2(1, 4);  k_relu_gemm<<<g2, 256>>>(gl1,  glob_w1, glob_b1, gl2, BATCH, 256,  512, 1);
        dim3 g3(1, 1);  k_relu_gemm<<<g3, 256>>>(gl2,  cls_w,   cls_b,   out, BATCH,  40,  256, 0);
    }
}

// round 17
// speedup vs baseline: 1.6310x; 1.0488x over previous
#include <cuda_runtime.h>
#include <cuda_bf16.h>
#include <math.h>
#include <stdint.h>

#define BATCH 32
#define NPTS  8192
#define SAM1  512
#define SAK1  32
#define SAM2  128
#define SAK2  64

// ---------------- static scratch (no runtime allocation) ----------------
__device__ float g_xyz [BATCH*NPTS*3];
__device__ float g_new1[BATCH*SAM1*3];
__device__ float g_new2[BATCH*SAM2*3];
__device__ int   g_idx1[BATCH*SAM1*SAK1];
__device__ int   g_idx2[BATCH*SAM2*SAK2];
__device__ float g_pool[BATCH*1024];
__device__ float g_gl1 [BATCH*512];
__device__ float g_gl2 [BATCH*256];
// bf16 hi/lo activation planes
__device__ __align__(16) __nv_bfloat16 g_INh[35651584], g_INl[35651584]; // 262144x136 max
__device__ __align__(16) __nv_bfloat16 g_P0h[33554432], g_P0l[33554432]; // 524288x64 max
__device__ __align__(16) __nv_bfloat16 g_P1h[33554432], g_P1l[33554432];
__device__ __align__(16) __nv_bfloat16 g_F1h[2097152],  g_F1l[2097152];  // 16384x128
__device__ __align__(16) __nv_bfloat16 g_F2h[1048576],  g_F2l[1048576];  // 4096x256
__device__ __align__(16) __nv_bfloat16 g_Wh [1048576],  g_Wl [1048576];  // all weights

__device__ __forceinline__ uint32_t smem_u32(const void* p) {
    uint32_t a;
    asm("{ .reg .u64 t; cvta.to.shared.u64 t, %1; cvt.u32.u64 %0, t; }" : "=r"(a) : "l"(p));
    return a;
}
__device__ __forceinline__ void split1(float v, __nv_bfloat16& h, __nv_bfloat16& l) {
    h = __float2bfloat16(v);
    l = __float2bfloat16(v - __bfloat162float(h));
}
__device__ __forceinline__ void split2(float a, float b, uint32_t& hi, uint32_t& lo) {
    __nv_bfloat16 ha, la, hb, lb;
    split1(a, ha, la); split1(b, hb, lb);
    hi = ((uint32_t)__bfloat16_as_ushort(hb) << 16) | __bfloat16_as_ushort(ha);
    lo = ((uint32_t)__bfloat16_as_ushort(lb) << 16) | __bfloat16_as_ushort(la);
}
__device__ __forceinline__ void ldm_x4(uint32_t* r, uint32_t addr) {
    asm volatile("ldmatrix.sync.aligned.m8n8.x4.shared.b16 {%0,%1,%2,%3}, [%4];"
                 : "=r"(r[0]), "=r"(r[1]), "=r"(r[2]), "=r"(r[3]) : "r"(addr));
}
__device__ __forceinline__ void ldm_x2(uint32_t* r, uint32_t addr) {
    asm volatile("ldmatrix.sync.aligned.m8n8.x2.shared.b16 {%0,%1}, [%2];"
                 : "=r"(r[0]), "=r"(r[1]) : "r"(addr));
}
__device__ __forceinline__ void mma16816(float* c, const uint32_t* a, const uint32_t* b) {
    asm volatile(
        "mma.sync.aligned.m16n8k16.row.col.f32.bf16.bf16.f32 "
        "{%0,%1,%2,%3}, {%4,%5,%6,%7}, {%8,%9}, {%0,%1,%2,%3};"
        : "+f"(c[0]), "+f"(c[1]), "+f"(c[2]), "+f"(c[3])
        : "r"(a[0]), "r"(a[1]), "r"(a[2]), "r"(a[3]), "r"(b[0]), "r"(b[1]));
}

// =====================================================================
// warp-MMA GEMM on pre-split bf16 planes, register-staged pipeline.
// (identical to the 2064us-measured R16 kernel)
// =====================================================================
__global__ void __launch_bounds__(256)
k_wmma(const __nv_bfloat16* __restrict__ Ahi, const __nv_bfloat16* __restrict__ Alo,
       const __nv_bfloat16* __restrict__ Whi, const __nv_bfloat16* __restrict__ Wlo,
       const float* __restrict__ bias, float* __restrict__ outF,
       __nv_bfloat16* __restrict__ outHi, __nv_bfloat16* __restrict__ outLo,
       int M, int N, int Ks, int poolk, int fp32out) {
    constexpr int STR = 40;                       // bf16 row stride (80B)
    __shared__ __align__(16) char sraw[34816];
    __shared__ float sbias[64];
    __nv_bfloat16 (*Ah)[STR] = reinterpret_cast<__nv_bfloat16(*)[STR]>(sraw);
    __nv_bfloat16 (*Al)[STR] = reinterpret_cast<__nv_bfloat16(*)[STR]>(sraw + 10240);
    __nv_bfloat16 (*Bh)[STR] = reinterpret_cast<__nv_bfloat16(*)[STR]>(sraw + 20480);
    __nv_bfloat16 (*Bl)[STR] = reinterpret_cast<__nv_bfloat16(*)[STR]>(sraw + 25600);
    float (*epi)[68] = reinterpret_cast<float(*)[68]>(sraw);

    const int tid = threadIdx.x, lane = tid & 31, wid = tid >> 5;
    const int wm = wid & 3, wn = wid >> 2;
    const int m0 = blockIdx.x * 128, n0 = blockIdx.y * 64;

    if (tid < 64) sbias[tid] = (n0 + tid < N) ? bias[n0 + tid] : 0.f;

    float acc[2][4][4];
#pragma unroll
    for (int mt = 0; mt < 2; mt++)
#pragma unroll
        for (int nt = 0; nt < 4; nt++)
#pragma unroll
            for (int v = 0; v < 4; v++) acc[mt][nt][v] = 0.f;

    const uint4 z4 = make_uint4(0, 0, 0, 0);
    const int nchunks = (Ks + 31) >> 5;
    const int ar0 = tid >> 2, ag = (tid & 3) * 8;
    const int br  = tid >> 2, bg = (tid & 3) * 8;

    uint4 a_h[2], a_l[2], b_h, b_l;
    {   // prefetch chunk 0
#pragma unroll
        for (int j = 0; j < 2; j++) {
            int r = ar0 + j*64;
            int gm = m0 + r, gk = ag;
            a_h[j] = z4; a_l[j] = z4;
            if (gm < M && gk < Ks) {
                size_t o = (size_t)gm*Ks + gk;
                a_h[j] = *(const uint4*)&Ahi[o];
                a_l[j] = *(const uint4*)&Alo[o];
            }
        }
        int gn = n0 + br, gk = bg;
        b_h = z4; b_l = z4;
        if (gn < N && gk < Ks) {
            size_t o = (size_t)gn*Ks + gk;
            b_h = *(const uint4*)&Whi[o];
            b_l = *(const uint4*)&Wlo[o];
        }
    }

    for (int ck = 0; ck < nchunks; ck++) {
#pragma unroll
        for (int j = 0; j < 2; j++) {
            int r = ar0 + j*64;
            *(uint4*)&Ah[r][ag] = a_h[j];
            *(uint4*)&Al[r][ag] = a_l[j];
        }
        *(uint4*)&Bh[br][bg] = b_h;
        *(uint4*)&Bl[br][bg] = b_l;
        __syncthreads();

        if (ck + 1 < nchunks) {
            const int kb = (ck + 1) << 5;
#pragma unroll
            for (int j = 0; j < 2; j++) {
                int r = ar0 + j*64;
                int gm = m0 + r, gk = kb + ag;
                a_h[j] = z4; a_l[j] = z4;
                if (gm < M && gk < Ks) {
                    size_t o = (size_t)gm*Ks + gk;
                    a_h[j] = *(const uint4*)&Ahi[o];
                    a_l[j] = *(const uint4*)&Alo[o];
                }
            }
            int gn = n0 + br, gk = kb + bg;
            b_h = z4; b_l = z4;
            if (gn < N && gk < Ks) {
                size_t o = (size_t)gn*Ks + gk;
                b_h = *(const uint4*)&Whi[o];
                b_l = *(const uint4*)&Wlo[o];
            }
        }

#pragma unroll
        for (int ks = 0; ks < 32; ks += 16) {
            uint32_t ah[2][4], al[2][4];
#pragma unroll
            for (int mt = 0; mt < 2; mt++) {
                int row = wm*32 + mt*16 + (lane & 7) + ((lane >> 3) & 1)*8;
                int kc  = ks + (lane >> 4)*8;
                ldm_x4(ah[mt], smem_u32(&Ah[row][kc]));
                ldm_x4(al[mt], smem_u32(&Al[row][kc]));
            }
            uint32_t bh[4][2], bl[4][2];
#pragma unroll
            for (int nt = 0; nt < 4; nt++) {
                int nr = wn*32 + nt*8 + (lane & 7);
                int kc = ks + ((lane >> 3) & 1)*8;
                ldm_x2(bh[nt], smem_u32(&Bh[nr][kc]));
                ldm_x2(bl[nt], smem_u32(&Bl[nr][kc]));
            }
#pragma unroll
            for (int mt = 0; mt < 2; mt++)
#pragma unroll
                for (int nt = 0; nt < 4; nt++) {
                    mma16816(acc[mt][nt], ah[mt], bh[nt]);
                    mma16816(acc[mt][nt], ah[mt], bl[nt]);
                    mma16816(acc[mt][nt], al[mt], bh[nt]);
                }
        }
        __syncthreads();
    }

    // ---- epilogue: bias + relu -> padded smem ----
    {
        int gid = lane >> 2, tig = lane & 3;
#pragma unroll
        for (int mt = 0; mt < 2; mt++)
#pragma unroll
            for (int nt = 0; nt < 4; nt++) {
                int r0 = wm*32 + mt*16 + gid;
                int cc = wn*32 + nt*8 + tig*2;
                epi[r0    ][cc    ] = fmaxf(acc[mt][nt][0] + sbias[cc    ], 0.f);
                epi[r0    ][cc + 1] = fmaxf(acc[mt][nt][1] + sbias[cc + 1], 0.f);
                epi[r0 + 8][cc    ] = fmaxf(acc[mt][nt][2] + sbias[cc    ], 0.f);
                epi[r0 + 8][cc + 1] = fmaxf(acc[mt][nt][3] + sbias[cc + 1], 0.f);
            }
    }
    __syncthreads();

    if (poolk == 0) {
#pragma unroll
        for (int j = 0; j < 4; j++) {
            int i = tid + j*256;
            int r = i >> 3, g = i & 7;
            int gm = m0 + r;
            if (gm < M) {
                const float* e = &epi[r][g*8];
                uint32_t h0,l0,h1,l1,h2,l2,h3,l3;
                split2(e[0], e[1], h0, l0);
                split2(e[2], e[3], h1, l1);
                split2(e[4], e[5], h2, l2);
                split2(e[6], e[7], h3, l3);
                size_t o = (size_t)gm*N + n0 + g*8;
                *(uint4*)&outHi[o] = make_uint4(h0, h1, h2, h3);
                *(uint4*)&outLo[o] = make_uint4(l0, l1, l2, l3);
            }
        }
    } else {
        int ng = 128 / poolk;
        for (int idx = tid; idx < 64*ng; idx += 256) {
            int c = idx & 63, g = idx >> 6;
            float mv = epi[g*poolk][c];
            for (int r = 1; r < poolk; r++) mv = fmaxf(mv, epi[g*poolk + r][c]);
            size_t o = (size_t)(m0/poolk + g)*N + n0 + c;
            if (fp32out) {
                outF[o] = mv;
            } else {
                __nv_bfloat16 h, l;
                split1(mv, h, l);
                outHi[o] = h; outLo[o] = l;
            }
        }
    }
}

// ---------------- merged weight split: all 9 layers in one launch ----------------
#define WSPLIT_TOT 800256
__global__ void k_wsplit_all(const float* __restrict__ w0, const float* __restrict__ w1,
                             const float* __restrict__ w2, const float* __restrict__ w3,
                             const float* __restrict__ w4, const float* __restrict__ w5,
                             const float* __restrict__ w6, const float* __restrict__ w7,
                             const float* __restrict__ w8,
                             __nv_bfloat16* __restrict__ hi, __nv_bfloat16* __restrict__ lo) {
    int i = blockIdx.x * blockDim.x + threadIdx.x;
    if (i >= WSPLIT_TOT) return;
    const int ends[9]  = {512, 4608, 12800, 30208, 46592, 79360, 144896, 275968, 800256};
    const int Karr[9]  = {3, 64, 64, 131, 128, 128, 256, 256, 512};
    const int Kparr[9] = {8, 64, 64, 136, 128, 128, 256, 256, 512};
    const float* ws[9] = {w0, w1, w2, w3, w4, w5, w6, w7, w8};
    int s = 0;
    while (i >= ends[s]) s++;
    int start = (s == 0) ? 0 : ends[s-1];
    int local = i - start;
    int Kp = Kparr[s], K = Karr[s];
    int n = local / Kp, c = local - n*Kp;
    float v = (c < K) ? ws[s][(size_t)n*K + c] : 0.f;
    __nv_bfloat16 h, l;
    split1(v, h, l);
    hi[i] = h; lo[i] = l;
}

// ---------------- transpose [B,3,N] -> [B,N,3] ----------------
__global__ void k_transpose(const float* __restrict__ pts, float* __restrict__ xyz) {
    int i = blockIdx.x * blockDim.x + threadIdx.x;
    if (i >= BATCH*3*NPTS) return;
    int b = i / (3*NPTS);
    int r = i - b*3*NPTS;
    int c = r / NPTS;
    int n = r - c*NPTS;
    xyz[((size_t)b*NPTS + n)*3 + c] = pts[i];
}

// ---------------- farthest point sampling ----------------
template<int NPT, int NTH>
__global__ void k_fps(const float* __restrict__ xyz, float* __restrict__ out_xyz,
                      int n, int m) {
    constexpr int NW = NTH/32;
    int b = blockIdx.x;
    const float* px = xyz + (size_t)b*n*3;
    float* out = out_xyz + (size_t)b*m*3;
    int t = threadIdx.x, lane = t & 31, w = t >> 5;

    float X[NPT], Y[NPT], Z[NPT], D[NPT];
#pragma unroll
    for (int i = 0; i < NPT; i++) {
        int p = t + i*NTH;
        X[i] = px[p*3]; Y[i] = px[p*3+1]; Z[i] = px[p*3+2];
        D[i] = 1e10f;
    }
    __shared__ float s_val[NW], s_x[NW], s_y[NW], s_z[NW];
    __shared__ int   s_idx[NW];
    __shared__ float s_l[3];
    if (t == 0) {
        s_l[0] = px[0]; s_l[1] = px[1]; s_l[2] = px[2];
        out[0] = px[0]; out[1] = px[1]; out[2] = px[2];
    }
    __syncthreads();

    for (int j = 1; j < m; j++) {
        float lx = s_l[0], ly = s_l[1], lz = s_l[2];
        float bv = -1.f, bx = 0.f, by = 0.f, bz = 0.f;
        int bi = 0;
#pragma unroll
        for (int i = 0; i < NPT; i++) {
            float dx = X[i]-lx, dy = Y[i]-ly, dz = Z[i]-lz;
            float d  = fmaf(dx, dx, fmaf(dy, dy, dz*dz));
            float nd = fminf(D[i], d);
            D[i] = nd;
            if (nd > bv) { bv = nd; bi = t + i*NTH; bx = X[i]; by = Y[i]; bz = Z[i]; }
        }
#pragma unroll
        for (int o = 16; o > 0; o >>= 1) {
            float ov = __shfl_down_sync(0xffffffffu, bv, o);
            int   oi = __shfl_down_sync(0xffffffffu, bi, o);
            float ox = __shfl_down_sync(0xffffffffu, bx, o);
            float oy = __shfl_down_sync(0xffffffffu, by, o);
            float oz = __shfl_down_sync(0xffffffffu, bz, o);
            if (ov > bv || (ov == bv && oi < bi)) { bv=ov; bi=oi; bx=ox; by=oy; bz=oz; }
        }
        if (lane == 0) { s_val[w]=bv; s_idx[w]=bi; s_x[w]=bx; s_y[w]=by; s_z[w]=bz; }
        __syncthreads();
        if (w == 0) {
            float v  = (lane < NW) ? s_val[lane] : -2.f;
            int   ii = (lane < NW) ? s_idx[lane] : 0x7fffffff;
            int   sl = lane;
#pragma unroll
            for (int o = 16; o > 0; o >>= 1) {
                float ov = __shfl_down_sync(0xffffffffu, v,  o);
                int   oi = __shfl_down_sync(0xffffffffu, ii, o);
                int   os = __shfl_down_sync(0xffffffffu, sl, o);
                if (ov > v || (ov == v && oi < ii)) { v=ov; ii=oi; sl=os; }
            }
            if (lane == 0) {
                float nx = s_x[sl], ny = s_y[sl], nz = s_z[sl];
                s_l[0] = nx; s_l[1] = ny; s_l[2] = nz;
                out[j*3] = nx; out[j*3+1] = ny; out[j*3+2] = nz;
            }
        }
        __syncthreads();
    }
}

// ---------------- ball query, warp-per-centroid (no barriers) ----------------
// first-KN valid (d2 < r2) in index order; pad with first valid index.
// Exactness vs reference proven in R12 (rel_err bit-identical to block version).
template<int KN>
__global__ void k_ball_query_w(const float* __restrict__ xyz, const float* __restrict__ cent,
                               int n, int mPerB, int totalM, float r2, int* __restrict__ out) {
    int wg = blockIdx.x * (blockDim.x >> 5) + (threadIdx.x >> 5);
    if (wg >= totalM) return;
    int lane = threadIdx.x & 31;
    int b = wg / mPerB;
    const float* px = xyz + (size_t)b*n*3;
    const float* c  = cent + (size_t)wg*3;
    float cx = c[0], cy = c[1], cz = c[2];
    int* o = out + (size_t)wg*KN;

    int cnt = 0;
    int first = -1;
    for (int base = 0; base < n && cnt < KN; base += 32) {
        int p = base + lane;
        bool valid = false;
        if (p < n) {
            float dx = px[p*3]-cx, dy = px[p*3+1]-cy, dz = px[p*3+2]-cz;
            valid = fmaf(dx, dx, fmaf(dy, dy, dz*dz)) < r2;
        }
        unsigned bal = __ballot_sync(0xffffffffu, valid);
        if (first < 0 && bal) first = base + __ffs(bal) - 1;
        int prefix = __popc(bal & ((1u << lane) - 1));
        if (valid && cnt + prefix < KN) o[cnt + prefix] = p;
        cnt += __popc(bal);
    }
    int c0 = (cnt < KN) ? cnt : KN;
    for (int i = c0 + lane; i < KN; i += 32) o[i] = first;
}

// ---------------- grouping: write pre-split bf16 planes ----------------
__global__ void k_group1(const float* __restrict__ xyz, const float* __restrict__ cent,
                         const int* __restrict__ idx,
                         __nv_bfloat16* __restrict__ Ahi, __nv_bfloat16* __restrict__ Alo) {
    int r = blockIdx.x * blockDim.x + threadIdx.x;
    if (r >= BATCH*SAM1*SAK1) return;
    int bm = r / SAK1;
    int b  = bm / SAM1;
    int i  = idx[r];
    const float* p = xyz + ((size_t)b*NPTS + i)*3;
    const float* c = cent + (size_t)bm*3;
    uint32_t h01, l01, h23, l23;
    split2(p[0]-c[0], p[1]-c[1], h01, l01);
    split2(p[2]-c[2], 0.f,       h23, l23);
    *(uint4*)&Ahi[(size_t)r*8] = make_uint4(h01, h23, 0, 0);
    *(uint4*)&Alo[(size_t)r*8] = make_uint4(l01, l23, 0, 0);
}

__global__ void k_group2(const float* __restrict__ xyz1, const float* __restrict__ cent2,
                         const int* __restrict__ idx,
                         const __nv_bfloat16* __restrict__ F1h, const __nv_bfloat16* __restrict__ F1l,
                         __nv_bfloat16* __restrict__ Ahi, __nv_bfloat16* __restrict__ Alo) {
    int e = blockIdx.x * blockDim.x + threadIdx.x;
    if (e >= BATCH*SAM2*SAK2*17) return;
    int g = e % 17;
    int r = e / 17;
    int bm = r / SAK2;
    int b  = bm / SAM2;
    int i  = idx[r];
    size_t frow = ((size_t)b*SAM1 + i)*128;
    uint32_t hw[4], lw[4];
#pragma unroll
    for (int q = 0; q < 4; q++) {
        float v0, v1;
        int c0 = g*8 + q*2, c1 = c0 + 1;
        if (c0 < 3)       v0 = xyz1[((size_t)b*SAM1 + i)*3 + c0] - cent2[(size_t)bm*3 + c0];
        else if (c0 < 131) v0 = __bfloat162float(F1h[frow + c0 - 3]) + __bfloat162float(F1l[frow + c0 - 3]);
        else              v0 = 0.f;
        if (c1 < 3)       v1 = xyz1[((size_t)b*SAM1 + i)*3 + c1] - cent2[(size_t)bm*3 + c1];
        else if (c1 < 131) v1 = __bfloat162float(F1h[frow + c1 - 3]) + __bfloat162float(F1l[frow + c1 - 3]);
        else              v1 = 0.f;
        split2(v0, v1, hw[q], lw[q]);
    }
    size_t o = (size_t)r*136 + g*8;
    *(uint4*)&Ahi[o] = make_uint4(hw[0], hw[1], hw[2], hw[3]);
    *(uint4*)&Alo[o] = make_uint4(lw[0], lw[1], lw[2], lw[3]);
}

// ---------------- fp32 GEMM for tiny M (glob/cls layers) ----------------
__global__ void k_relu_gemm(const float* __restrict__ A, const float* __restrict__ W,
                            const float* __restrict__ bias, float* __restrict__ C,
                            int M, int Nn, int K, int relu) {
    __shared__ float As[16][128];
    __shared__ float Ws[16][64];
    int m0 = blockIdx.x * 128;
    int n0 = blockIdx.y * 64;
    int tid = threadIdx.x;
    int tx = tid & 15;
    int ty = tid >> 4;
    float acc[8][4] = {};
    for (int k0 = 0; k0 < K; k0 += 16) {
#pragma unroll
        for (int r = 0; r < 8; r++) {
            int lin = tid + r*256;
            int mm = lin >> 4, kk = lin & 15;
            int gm = m0 + mm, gk = k0 + kk;
            As[kk][mm] = (gm < M && gk < K) ? A[(size_t)gm*K + gk] : 0.f;
        }
#pragma unroll
        for (int r = 0; r < 4; r++) {
            int lin = tid + r*256;
            int nn = lin >> 4, kk = lin & 15;
            int gn = n0 + nn, gk = k0 + kk;
            Ws[kk][nn] = (gn < Nn && gk < K) ? W[(size_t)gn*K + gk] : 0.f;
        }
        __syncthreads();
#pragma unroll
        for (int kk = 0; kk < 16; kk++) {
            float a[8], w[4];
#pragma unroll
            for (int i = 0; i < 8; i++) a[i] = As[kk][ty*8 + i];
#pragma unroll
            for (int j = 0; j < 4; j++) w[j] = Ws[kk][tx*4 + j];
#pragma unroll
            for (int i = 0; i < 8; i++)
#pragma unroll
                for (int j = 0; j < 4; j++)
                    acc[i][j] = fmaf(a[i], w[j], acc[i][j]);
        }
        __syncthreads();
    }
#pragma unroll
    for (int i = 0; i < 8; i++) {
        int gm = m0 + ty*8 + i;
        if (gm >= M) continue;
#pragma unroll
        for (int j = 0; j < 4; j++) {
            int gn = n0 + tx*4 + j;
            if (gn >= Nn) continue;
            float v = acc[i][j] + bias[gn];
            if (relu) v = fmaxf(v, 0.f);
            C[(size_t)gm*Nn + gn] = v;
        }
    }
}

extern "C" void kernel_launch(void* const* d_in, const int* in_sizes, int n_in,
                              void* d_out, int out_size) {
    const float* pts     = (const float*)d_in[0];
    const float* sa1_w0  = (const float*)d_in[1];  const float* sa1_b0 = (const float*)d_in[2];
    const float* sa1_w1  = (const float*)d_in[3];  const float* sa1_b1 = (const float*)d_in[4];
    const float* sa1_w2  = (const float*)d_in[5];  const float* sa1_b2 = (const float*)d_in[6];
    const float* sa2_w0  = (const float*)d_in[7];  const float* sa2_b0 = (const float*)d_in[8];
    const float* sa2_w1  = (const float*)d_in[9];  const float* sa2_b1 = (const float*)d_in[10];
    const float* sa2_w2  = (const float*)d_in[11]; const float* sa2_b2 = (const float*)d_in[12];
    const float* loc_w0  = (const float*)d_in[13]; const float* loc_b0 = (const float*)d_in[14];
    const float* loc_w1  = (const float*)d_in[15]; const float* loc_b1 = (const float*)d_in[16];
    const float* loc_w2  = (const float*)d_in[17]; const float* loc_b2 = (const float*)d_in[18];
    const float* glob_w0 = (const float*)d_in[19]; const float* glob_b0 = (const float*)d_in[20];
    const float* glob_w1 = (const float*)d_in[21]; const float* glob_b1 = (const float*)d_in[22];
    const float* cls_w   = (const float*)d_in[23]; const float* cls_b  = (const float*)d_in[24];
    float* out = (float*)d_out;

    float *xyz, *new1, *new2, *pool, *gl1, *gl2;
    int *idx1, *idx2;
    __nv_bfloat16 *INh, *INl, *P0h, *P0l, *P1h, *P1l, *F1h, *F1l, *F2h, *F2l, *Wh, *Wl;
    cudaGetSymbolAddress((void**)&xyz,  g_xyz);
    cudaGetSymbolAddress((void**)&new1, g_new1);
    cudaGetSymbolAddress((void**)&new2, g_new2);
    cudaGetSymbolAddress((void**)&idx1, g_idx1);
    cudaGetSymbolAddress((void**)&idx2, g_idx2);
    cudaGetSymbolAddress((void**)&pool, g_pool);
    cudaGetSymbolAddress((void**)&gl1,  g_gl1);
    cudaGetSymbolAddress((void**)&gl2,  g_gl2);
    cudaGetSymbolAddress((void**)&INh,  g_INh);  cudaGetSymbolAddress((void**)&INl, g_INl);
    cudaGetSymbolAddress((void**)&P0h,  g_P0h);  cudaGetSymbolAddress((void**)&P0l, g_P0l);
    cudaGetSymbolAddress((void**)&P1h,  g_P1h);  cudaGetSymbolAddress((void**)&P1l, g_P1l);
    cudaGetSymbolAddress((void**)&F1h,  g_F1h);  cudaGetSymbolAddress((void**)&F1l, g_F1l);
    cudaGetSymbolAddress((void**)&F2h,  g_F2h);  cudaGetSymbolAddress((void**)&F2l, g_F2l);
    cudaGetSymbolAddress((void**)&Wh,   g_Wh);   cudaGetSymbolAddress((void**)&Wl,  g_Wl);

    // weight plane offsets (elems; consecutive segments, see k_wsplit_all)
    const int oW0 = 0,      oW1 = 512,    oW2 = 4608,   oW3 = 12800,  oW4 = 30208;
    const int oW5 = 46592,  oW6 = 79360,  oW7 = 144896, oW8 = 275968;
    k_wsplit_all<<<(WSPLIT_TOT + 255)/256, 256>>>(sa1_w0, sa1_w1, sa1_w2, sa2_w0, sa2_w1,
                                                  sa2_w2, loc_w0, loc_w1, loc_w2, Wh, Wl);

    // transpose points -> xyz [B,N,3]
    k_transpose<<<(BATCH*3*NPTS + 255)/256, 256>>>(pts, xyz);

    // ---- SA1 ----
    k_fps<8, 1024><<<BATCH, 1024>>>(xyz, new1, NPTS, SAM1);
    {
        const int totalM = BATCH*SAM1;          // 16384 warps, 8/block
        k_ball_query_w<SAK1><<<(totalM + 7)/8, 256>>>(xyz, new1, NPTS, SAM1, totalM, 0.2f*0.2f, idx1);
    }
    k_group1<<<(BATCH*SAM1*SAK1 + 255)/256, 256>>>(xyz, new1, idx1, INh, INl);
    {
        const int M = BATCH*SAM1*SAK1;          // 524288
        k_wmma<<<dim3(M/128, 1), 256>>>(INh, INl, Wh+oW0, Wl+oW0, sa1_b0, nullptr, P0h, P0l, M,  64,   8,  0, 0);
        k_wmma<<<dim3(M/128, 1), 256>>>(P0h, P0l, Wh+oW1, Wl+oW1, sa1_b1, nullptr, P1h, P1l, M,  64,  64,  0, 0);
        k_wmma<<<dim3(M/128, 2), 256>>>(P1h, P1l, Wh+oW2, Wl+oW2, sa1_b2, nullptr, F1h, F1l, M, 128,  64, 32, 0);
    }

    // ---- SA2 ----
    k_fps<1, 512><<<BATCH, 512>>>(new1, new2, SAM1, SAM2);
    {
        const int totalM = BATCH*SAM2;          // 4096 warps
        k_ball_query_w<SAK2><<<(totalM + 7)/8, 256>>>(new1, new2, SAM1, SAM2, totalM, 0.4f*0.4f, idx2);
    }
    {
        int tot = BATCH*SAM2*SAK2*17;
        k_group2<<<(tot + 255)/256, 256>>>(new1, new2, idx2, F1h, F1l, INh, INl);
        const int M = BATCH*SAM2*SAK2;          // 262144
        k_wmma<<<dim3(M/128, 2), 256>>>(INh, INl, Wh+oW3, Wl+oW3, sa2_b0, nullptr, P0h, P0l, M, 128, 136,  0, 0);
        k_wmma<<<dim3(M/128, 2), 256>>>(P0h, P0l, Wh+oW4, Wl+oW4, sa2_b1, nullptr, P1h, P1l, M, 128, 128,  0, 0);
        k_wmma<<<dim3(M/128, 4), 256>>>(P1h, P1l, Wh+oW5, Wl+oW5, sa2_b2, nullptr, F2h, F2l, M, 256, 128, 64, 0);
    }

    // ---- local MLP + fused global max-pool ----
    {
        const int M = BATCH*SAM2;               // 4096
        k_wmma<<<dim3(M/128,  4), 256>>>(F2h, F2l, Wh+oW6, Wl+oW6, loc_b0, nullptr, P0h, P0l, M,  256, 256,   0, 0);
        k_wmma<<<dim3(M/128,  8), 256>>>(P0h, P0l, Wh+oW7, Wl+oW7, loc_b1, nullptr, P1h, P1l, M,  512, 256,   0, 0);
        k_wmma<<<dim3(M/128, 16), 256>>>(P1h, P1l, Wh+oW8, Wl+oW8, loc_b2, pool, nullptr, nullptr, M, 1024, 512, 128, 1);
    }

    // ---- global MLP + classifier (tiny M=32, fp32 path) ----
    {
        dim3 g1(1, 8);  k_relu_gemm<<<g1, 256>>>(pool, glob_w0, glob_b0, gl1, BATCH, 512, 1024, 1);
        dim3 g2(1, 4);  k_relu_gemm<<<g2, 256>>>(gl1,  glob_w1, glob_b1, gl2, BATCH, 256,  512, 1);
        dim3 g3(1, 1);  k_relu_gemm<<<g3, 256>>>(gl2,  cls_w,   cls_b,   out, BATCH,  40,  256, 0);
    }
}